// round 14
// baseline (speedup 1.0000x reference)
#include <cuda_runtime.h>
#include <cuda_bf16.h>
#include <cstdint>

#define BATCH 2
#define CH    512
#define TIME  2048
#define DIM   64
#define TT    8
#define NC    16      // Chebyshev coefficients (degree 15)
#define NN    64      // fit nodes
#define XR    5.7f    // fit half-range
#define L2E_F 1.44269504088896340736f
#define PI_F  3.14159265358979323846f

// Attention output, bf16, TRANSPOSED layout [B][T][C] (c contiguous).
__device__ __nv_bfloat16 g_attnT[BATCH * TIME * CH];
// W pre-converted to bf16 (filled by attn_kernel).
__device__ __nv_bfloat16 g_Wbf[CH * CH];

__device__ __forceinline__ float ex2f(float v) {
    float r;
    asm("ex2.approx.f32 %0, %1;" : "=f"(r) : "f"(v));
    return r;
}
__device__ __forceinline__ float cosfast(float v) {
    float r;
    asm("cos.approx.f32 %0, %1;" : "=f"(r) : "f"(v));
    return r;
}

// ---------------------------------------------------------------------------
// Kernel A: linear attention via Chebyshev moment collapse, G fused in-block.
//   G phase (redundant per block, parallel across chip):
//     warp w owns d = 8w..8w+7; 4 lanes per d, 16 nodes per lane.
//     Fit phi_q, phi_k*(wv x+bv), phi_k -> collapse: G = Cq^T * {CS, CZ}.
//   Attention phase (warp per t, TT=8):
//     moments M_j = sum_c T_j(x_c/XR);  A = Gn*M, B = Gd*M;
//     out(c) = (sum A_j T_j) / (sum B_j T_j).
// ---------------------------------------------------------------------------
__global__ __launch_bounds__(256) void attn_kernel(
    const float* __restrict__ x, const float* __restrict__ W,
    const float* __restrict__ wq, const float* __restrict__ bq,
    const float* __restrict__ wk, const float* __restrict__ bk,
    const float* __restrict__ wv, const float* __restrict__ bv)
{
    __shared__ float xs[TT][CH];                       // 16 KB
    __shared__ float s_cq[DIM][NC], s_cS[DIM][NC], s_cZ[DIM][NC];  // 12 KB
    __shared__ float sGn[NC * NC], sGd[NC * NC];       // 2 KB
    __shared__ float sA[TT][NC], sB[TT][NC];

    const int tile = blockIdx.x;          // 512 tiles
    const int b    = tile >> 8;           // TIME/TT = 256
    const int t0   = (tile & 255) * TT;
    const int tid  = threadIdx.x;
    const int wid  = tid >> 5;
    const int lane = tid & 31;

    // W -> bf16 (512 blocks x 256 threads x 2 = 512*512)
    {
        int wi = tile * 512 + tid;
        g_Wbf[wi]       = __float2bfloat16_rn(W[wi]);
        g_Wbf[wi + 256] = __float2bfloat16_rn(W[wi + 256]);
    }

    // ---- G phase: Chebyshev fits ----
    {
        const int d   = (wid << 3) + (lane >> 2);   // 8 d per warp
        const int sub = lane & 3;                   // node group 0..3
        const float wqd = wq[d], bqd = bq[d];
        const float wkd = wk[d], bkd = bk[d];
        const float wvv = __ldg(wv), bvv = __ldg(bv);

        float aq[NC], aS[NC], aZ[NC];
        #pragma unroll
        for (int j = 0; j < NC; j++) { aq[j] = 0.f; aS[j] = 0.f; aZ[j] = 0.f; }

        #pragma unroll
        for (int ii = 0; ii < NN / 4; ii++) {
            int i = sub * (NN / 4) + ii;
            float xi = cosfast(PI_F * (i + 0.5f) / NN);    // node in [-1,1]
            float xx = XR * xi;
            float uq = fmaf(wqd, xx, bqd);
            float uk = fmaf(wkd, xx, bkd);
            float pq = ex2f(fminf(uq, 0.f) * L2E_F) + fmaxf(uq, 0.f);
            float pk = ex2f(fminf(uk, 0.f) * L2E_F) + fmaxf(uk, 0.f);
            float hS = pk * fmaf(wvv, xx, bvv);
            float tm = 1.f, tc = xi;
            aq[0] += pq; aS[0] += hS; aZ[0] += pk;
            #pragma unroll
            for (int j = 1; j < NC; j++) {
                aq[j] = fmaf(pq, tc, aq[j]);
                aS[j] = fmaf(hS, tc, aS[j]);
                aZ[j] = fmaf(pk, tc, aZ[j]);
                float tn = fmaf(2.f * xi, tc, -tm); tm = tc; tc = tn;
            }
        }
        // reduce across the 4 lanes of this d
        #pragma unroll
        for (int off = 1; off <= 2; off <<= 1) {
            #pragma unroll
            for (int j = 0; j < NC; j++) {
                aq[j] += __shfl_xor_sync(0xffffffffu, aq[j], off);
                aS[j] += __shfl_xor_sync(0xffffffffu, aS[j], off);
                aZ[j] += __shfl_xor_sync(0xffffffffu, aZ[j], off);
            }
        }
        if (sub == 0) {
            #pragma unroll
            for (int j = 0; j < NC; j++) {
                float s = (j == 0 ? 1.f : 2.f) / NN;
                s_cq[d][j] = aq[j] * s;
                s_cS[d][j] = aS[j] * s;
                s_cZ[d][j] = aZ[j] * s;
            }
        }
    }

    // Load x[b, :, t0:t0+8] -> xs[t][c]
    const float* xg = x + (size_t)b * CH * TIME + t0;
    for (int i = tid; i < CH * (TT / 4); i += 256) {
        int c = i >> 1, j = (i & 1) * 4;
        float4 v = *reinterpret_cast<const float4*>(&xg[(size_t)c * TIME + j]);
        xs[j + 0][c] = v.x; xs[j + 1][c] = v.y;
        xs[j + 2][c] = v.z; xs[j + 3][c] = v.w;
    }
    __syncthreads();

    // ---- collapse: G[jp][j] = sum_d cq[d][jp] * {cS,cZ}[d][j] ----
    {
        int jp = tid >> 4, j = tid & 15;
        float gn = 0.f, gd = 0.f;
        #pragma unroll 8
        for (int d = 0; d < DIM; d++) {
            float q = s_cq[d][jp];
            gn = fmaf(q, s_cS[d][j], gn);
            gd = fmaf(q, s_cZ[d][j], gd);
        }
        sGn[tid] = gn;
        sGd[tid] = gd;
    }
    __syncthreads();

    const int t = wid;
    const float invXR = 1.f / XR;

    // ---- moments (j = 1..15; M_0 = CH) ----
    float M[NC];
    #pragma unroll
    for (int j = 1; j < NC; j++) M[j] = 0.f;
    #pragma unroll
    for (int k = 0; k < 16; k++) {
        float xi = fminf(fmaxf(xs[t][lane + 32 * k] * invXR, -1.f), 1.f);
        float tm = 1.f, tc = xi;
        M[1] += xi;
        #pragma unroll
        for (int j = 2; j < NC; j++) {
            float tn = fmaf(2.f * xi, tc, -tm);
            M[j] += tn; tm = tc; tc = tn;
        }
    }
    #pragma unroll
    for (int off = 16; off; off >>= 1) {
        #pragma unroll
        for (int j = 1; j < NC; j++)
            M[j] += __shfl_xor_sync(0xffffffffu, M[j], off);
    }

    // ---- matvecs: lanes 0..15 -> A_j', lanes 16..31 -> B_j' ----
    {
        int jj = lane & 15;
        const float* Gp = (lane < 16) ? sGn : sGd;
        float a = Gp[jj * NC] * (float)CH;     // M_0 = CH
        #pragma unroll
        for (int j = 1; j < NC; j++) a = fmaf(Gp[jj * NC + j], M[j], a);
        float* dst = (lane < 16) ? &sA[t][jj] : &sB[t][jj];
        *dst = a;
    }
    __syncwarp();

    float Ar[NC], Br[NC];
    #pragma unroll
    for (int j = 0; j < NC; j++) { Ar[j] = sA[t][j]; Br[j] = sB[t][j]; }

    // ---- per-element eval ----
    #pragma unroll
    for (int k = 0; k < 16; k++) {
        int c = lane + 32 * k;
        float xi = fminf(fmaxf(xs[t][c] * invXR, -1.f), 1.f);
        float tm = 1.f, tc = xi;
        float num = fmaf(Ar[1], xi, Ar[0]);
        float den = fmaf(Br[1], xi, Br[0]);
        #pragma unroll
        for (int j = 2; j < NC; j++) {
            float tn = fmaf(2.f * xi, tc, -tm);
            num = fmaf(Ar[j], tn, num);
            den = fmaf(Br[j], tn, den);
            tm = tc; tc = tn;
        }
        xs[t][c] = __fdividef(num, den);
    }
    __syncthreads();

    // Coalesced bf16 store: g_attnT[b][t0+tt][c]
    __nv_bfloat162* op = reinterpret_cast<__nv_bfloat162*>(
        g_attnT + ((size_t)b * TIME + t0) * CH);
    for (int i = tid; i < TT * (CH / 2); i += 256) {
        int tt = i >> 8, cp = i & 255;
        op[tt * 256 + cp] =
            __floats2bfloat162_rn(xs[tt][2 * cp], xs[tt][2 * cp + 1]);
    }
}

// ---------------------------------------------------------------------------
// Kernel B (UNCHANGED from R12/R13 — measured 22.4us):
// out[b,o,t] = x[b,o,t] + b_proj[o] + sum_c W[o,c]*attn[b,c,t]
// bf16 mma m16n8k16 + ldmatrix.x4 + 3-stage cp.async pipeline.
// ---------------------------------------------------------------------------
#define PBM 64
#define PBN 64
#define PBK 64
#define KST (PBK + 8)
#define NSTG 3
#define BUF_HALVES (PBM * KST)
#define SMEM_BYTES (NSTG * 2 * BUF_HALVES * 2)

__device__ __forceinline__ void cp16(uint32_t dst, const void* src) {
    asm volatile("cp.async.cg.shared.global [%0], [%1], 16;" :: "r"(dst), "l"(src));
}
__device__ __forceinline__ void ldsm_x4(uint32_t r[4], uint32_t addr) {
    asm volatile("ldmatrix.sync.aligned.m8n8.x4.shared.b16 {%0,%1,%2,%3}, [%4];"
                 : "=r"(r[0]), "=r"(r[1]), "=r"(r[2]), "=r"(r[3]) : "r"(addr));
}
__device__ __forceinline__ void mma_bf16(float c[4], const uint32_t a[4], const uint32_t b0, const uint32_t b1) {
    asm("mma.sync.aligned.m16n8k16.row.col.f32.bf16.bf16.f32 "
        "{%0,%1,%2,%3}, {%4,%5,%6,%7}, {%8,%9}, {%0,%1,%2,%3};"
        : "+f"(c[0]), "+f"(c[1]), "+f"(c[2]), "+f"(c[3])
        : "r"(a[0]), "r"(a[1]), "r"(a[2]), "r"(a[3]), "r"(b0), "r"(b1));
}

__global__ __launch_bounds__(128) void proj_kernel(
    const float* __restrict__ bp,
    const float* __restrict__ x, float* __restrict__ out)
{
    extern __shared__ __nv_bfloat16 smem[];
    __nv_bfloat16* Abuf = smem;
    __nv_bfloat16* Bbuf = smem + NSTG * BUF_HALVES;

    const int b   = blockIdx.z;
    const int m0  = blockIdx.y * PBM;
    const int n0  = blockIdx.x * PBN;
    const int tid = threadIdx.x;
    const int wid  = tid >> 5;
    const int lane = tid & 31;
    const int g  = lane >> 2;
    const int tg = lane & 3;
    const int wm = (wid >> 1) * 32;
    const int wn = (wid & 1) * 32;

    const __nv_bfloat16* Bg = g_attnT + (size_t)b * TIME * CH;

    const int srow = tid >> 1;
    const int skb  = (tid & 1) * 32;

    const uint32_t sa0 = (uint32_t)__cvta_generic_to_shared(Abuf);
    const uint32_t sb0 = (uint32_t)__cvta_generic_to_shared(Bbuf);
    const uint32_t stg_bytes = BUF_HALVES * 2;

    float acc[2][4][4];
    #pragma unroll
    for (int i = 0; i < 2; i++)
        #pragma unroll
        for (int j = 0; j < 4; j++)
            #pragma unroll
            for (int r = 0; r < 4; r++) acc[i][j][r] = 0.f;

    auto stage = [&](int s, int k0) {
        const __nv_bfloat16* sA = &g_Wbf[(size_t)(m0 + srow) * CH + k0 + skb];
        const __nv_bfloat16* sB = &Bg[(size_t)(n0 + srow) * CH + k0 + skb];
        uint32_t da = sa0 + s * stg_bytes + (srow * KST + skb) * 2;
        uint32_t db = sb0 + s * stg_bytes + (srow * KST + skb) * 2;
        #pragma unroll
        for (int i = 0; i < 4; i++) {
            cp16(da + i * 16, sA + i * 8);
            cp16(db + i * 16, sB + i * 8);
        }
    };

    stage(0, 0);
    asm volatile("cp.async.commit_group;");
    stage(1, PBK);
    asm volatile("cp.async.commit_group;");

    const int a_row = wm + (lane & 15);
    const int a_k   = ((lane >> 4) & 1) * 8;
    const int b_row = wn + (lane & 7) + ((lane >> 4) & 1) * 8;
    const int b_k   = ((lane >> 3) & 1) * 8;

    const int NIT = CH / PBK;   // 8
    int s = 0;
    for (int it = 0; it < NIT; it++) {
        if (it + 1 < NIT) {
            asm volatile("cp.async.wait_group 1;");
        } else {
            asm volatile("cp.async.wait_group 0;");
        }
        __syncthreads();

        if (it + 2 < NIT) {
            int s2 = s + 2 >= NSTG ? s + 2 - NSTG : s + 2;
            stage(s2, (it + 2) * PBK);
            asm volatile("cp.async.commit_group;");
        }

        const uint32_t ab = sa0 + s * stg_bytes;
        const uint32_t bb = sb0 + s * stg_bytes;

        #pragma unroll
        for (int kk = 0; kk < PBK; kk += 16) {
            uint32_t a[2][4], bf[2][4];
            #pragma unroll
            for (int fm = 0; fm < 2; fm++)
                ldsm_x4(a[fm], ab + ((a_row + fm * 16) * KST + kk + a_k) * 2);
            #pragma unroll
            for (int bh = 0; bh < 2; bh++)
                ldsm_x4(bf[bh], bb + ((b_row + bh * 16) * KST + kk + b_k) * 2);
            #pragma unroll
            for (int fm = 0; fm < 2; fm++)
                #pragma unroll
                for (int bh = 0; bh < 2; bh++) {
                    mma_bf16(acc[fm][bh * 2 + 0], a[fm], bf[bh][0], bf[bh][1]);
                    mma_bf16(acc[fm][bh * 2 + 1], a[fm], bf[bh][2], bf[bh][3]);
                }
        }
        s = (s + 1 >= NSTG) ? 0 : s + 1;
    }

    const float* xb = x + (size_t)b * CH * TIME;
    float*       ob = out + (size_t)b * CH * TIME;
    #pragma unroll
    for (int fm = 0; fm < 2; fm++) {
        int row0 = m0 + wm + fm * 16 + g;
        float bias0 = bp[row0];
        float bias1 = bp[row0 + 8];
        #pragma unroll
        for (int fn = 0; fn < 4; fn++) {
            int col = n0 + wn + fn * 8 + tg * 2;
            size_t off0 = (size_t)row0 * TIME + col;
            size_t off1 = (size_t)(row0 + 8) * TIME + col;
            float2 x0 = *reinterpret_cast<const float2*>(&xb[off0]);
            float2 x1 = *reinterpret_cast<const float2*>(&xb[off1]);
            float2 o0, o1;
            o0.x = x0.x + bias0 + acc[fm][fn][0];
            o0.y = x0.y + bias0 + acc[fm][fn][1];
            o1.x = x1.x + bias1 + acc[fm][fn][2];
            o1.y = x1.y + bias1 + acc[fm][fn][3];
            *reinterpret_cast<float2*>(&ob[off0]) = o0;
            *reinterpret_cast<float2*>(&ob[off1]) = o1;
        }
    }
}

// ---------------------------------------------------------------------------
extern "C" void kernel_launch(void* const* d_in, const int* in_sizes, int n_in,
                              void* d_out, int out_size) {
    const float* x  = (const float*)d_in[0];
    const float* wq = (const float*)d_in[1];
    const float* bq = (const float*)d_in[2];
    const float* wk = (const float*)d_in[3];
    const float* bk = (const float*)d_in[4];
    const float* wv = (const float*)d_in[5];
    const float* bv = (const float*)d_in[6];
    const float* wp = (const float*)d_in[7];
    const float* bp = (const float*)d_in[8];
    float* out = (float*)d_out;

    cudaFuncSetAttribute(proj_kernel,
                         cudaFuncAttributeMaxDynamicSharedMemorySize,
                         SMEM_BYTES);

    attn_kernel<<<BATCH * (TIME / TT), 256>>>(x, wp, wq, bq, wk, bk, wv, bv);

    dim3 grid(TIME / PBN, CH / PBM, BATCH);
    proj_kernel<<<grid, 128, SMEM_BYTES>>>(bp, x, out);
}

// round 17
// speedup vs baseline: 1.2087x; 1.2087x over previous
#include <cuda_runtime.h>
#include <cuda_bf16.h>
#include <cstdint>

#define BATCH 2
#define CH    512
#define TIME  2048
#define DIM   64
#define TT    8
#define NC    16      // Chebyshev coefficients (degree 15)
#define NN    64      // fit nodes
#define XR    5.7f    // fit half-range
#define L2E_F 1.44269504088896340736f
#define PI_F  3.14159265358979323846f

// Attention output, bf16, TRANSPOSED layout [B][T][C] (c contiguous).
__device__ __nv_bfloat16 g_attnT[BATCH * TIME * CH];
// W pre-converted to bf16 (filled by attn_kernel).
__device__ __nv_bfloat16 g_Wbf[CH * CH];
// Collapsed Chebyshev operators: num/den 16x16 matrices.
__device__ float g_Gnum[NC * NC];
__device__ float g_Gden[NC * NC];

__device__ __forceinline__ float ex2f(float v) {
    float r;
    asm("ex2.approx.f32 %0, %1;" : "=f"(r) : "f"(v));
    return r;
}
__device__ __forceinline__ float cosfast(float v) {
    float r;
    asm("cos.approx.f32 %0, %1;" : "=f"(r) : "f"(v));
    return r;
}

// ---------------------------------------------------------------------------
// Prologue (1 block, 256 threads, PARALLEL):
//   warp w owns d = 8w..8w+7; 4 lanes per d, 16 nodes per lane.
//   Chebyshev-fit phi_q, phi_k*(wv x+bv), phi_k over x in [-XR,XR], then
//   collapse over d:  G{num,den}[j'][j] = sum_d cq[d][j'] * {cS,cZ}[d][j].
// ---------------------------------------------------------------------------
__global__ __launch_bounds__(256) void cheb_prologue(
    const float* __restrict__ wq, const float* __restrict__ bq,
    const float* __restrict__ wk, const float* __restrict__ bk,
    const float* __restrict__ wv, const float* __restrict__ bv)
{
    __shared__ float s_cq[DIM][NC], s_cS[DIM][NC], s_cZ[DIM][NC];
    const int tid  = threadIdx.x;
    const int wid  = tid >> 5;
    const int lane = tid & 31;

    {
        const int d   = (wid << 3) + (lane >> 2);   // 8 d per warp
        const int sub = lane & 3;                   // node group 0..3
        const float wqd = wq[d], bqd = bq[d];
        const float wkd = wk[d], bkd = bk[d];
        const float wvv = __ldg(wv), bvv = __ldg(bv);

        float aq[NC], aS[NC], aZ[NC];
        #pragma unroll
        for (int j = 0; j < NC; j++) { aq[j] = 0.f; aS[j] = 0.f; aZ[j] = 0.f; }

        #pragma unroll
        for (int ii = 0; ii < NN / 4; ii++) {
            int i = sub * (NN / 4) + ii;
            float xi = cosfast(PI_F * (i + 0.5f) / NN);    // node in [-1,1]
            float xx = XR * xi;
            float uq = fmaf(wqd, xx, bqd);
            float uk = fmaf(wkd, xx, bkd);
            float pq = ex2f(fminf(uq, 0.f) * L2E_F) + fmaxf(uq, 0.f);
            float pk = ex2f(fminf(uk, 0.f) * L2E_F) + fmaxf(uk, 0.f);
            float hS = pk * fmaf(wvv, xx, bvv);
            float tm = 1.f, tc = xi;
            aq[0] += pq; aS[0] += hS; aZ[0] += pk;
            #pragma unroll
            for (int j = 1; j < NC; j++) {
                aq[j] = fmaf(pq, tc, aq[j]);
                aS[j] = fmaf(hS, tc, aS[j]);
                aZ[j] = fmaf(pk, tc, aZ[j]);
                float tn = fmaf(2.f * xi, tc, -tm); tm = tc; tc = tn;
            }
        }
        // reduce across the 4 lanes of this d
        #pragma unroll
        for (int off = 1; off <= 2; off <<= 1) {
            #pragma unroll
            for (int j = 0; j < NC; j++) {
                aq[j] += __shfl_xor_sync(0xffffffffu, aq[j], off);
                aS[j] += __shfl_xor_sync(0xffffffffu, aS[j], off);
                aZ[j] += __shfl_xor_sync(0xffffffffu, aZ[j], off);
            }
        }
        if (sub == 0) {
            #pragma unroll
            for (int j = 0; j < NC; j++) {
                float s = (j == 0 ? 1.f : 2.f) / NN;
                s_cq[d][j] = aq[j] * s;
                s_cS[d][j] = aS[j] * s;
                s_cZ[d][j] = aZ[j] * s;
            }
        }
    }
    __syncthreads();

    // 256 threads -> 256 entries per matrix
    {
        int jp = tid >> 4, j = tid & 15;
        float gn = 0.f, gd = 0.f;
        #pragma unroll 8
        for (int d = 0; d < DIM; d++) {
            float q = s_cq[d][jp];
            gn = fmaf(q, s_cS[d][j], gn);
            gd = fmaf(q, s_cZ[d][j], gd);
        }
        g_Gnum[tid] = gn;
        g_Gden[tid] = gd;
    }
}

// ---------------------------------------------------------------------------
// Kernel A (R13 structure — measured ~10us): Chebyshev moment collapse.
// Per (b, 8-t tile), warp per t:
//   1. moments M_j = sum_c T_j(x_c/XR)           (j=0..15; M_0 = 512)
//   2. A = G_num * M, B = G_den * M              (16x16 matvecs)
//   3. out(c) = (sum_j A_j T_j(xi_c)) / (sum_j B_j T_j(xi_c))
// ---------------------------------------------------------------------------
__global__ __launch_bounds__(256) void attn_kernel(
    const float* __restrict__ x, const float* __restrict__ W)
{
    __shared__ float xs[TT][CH];          // 16 KB
    __shared__ float sA[TT][NC], sB[TT][NC];
    __shared__ float sGn[NC * NC], sGd[NC * NC];

    const int tile = blockIdx.x;          // 512 tiles
    const int b    = tile >> 8;           // TIME/TT = 256
    const int t0   = (tile & 255) * TT;
    const int tid  = threadIdx.x;
    const int wid  = tid >> 5;
    const int lane = tid & 31;

    // W -> bf16 (512 blocks x 256 threads x 2 = 512*512)
    {
        int wi = tile * 512 + tid;
        g_Wbf[wi]       = __float2bfloat16_rn(W[wi]);
        g_Wbf[wi + 256] = __float2bfloat16_rn(W[wi + 256]);
    }
    sGn[tid] = g_Gnum[tid];
    sGd[tid] = g_Gden[tid];

    // Load x[b, :, t0:t0+8] -> xs[t][c]
    const float* xg = x + (size_t)b * CH * TIME + t0;
    for (int i = tid; i < CH * (TT / 4); i += 256) {
        int c = i >> 1, j = (i & 1) * 4;
        float4 v = *reinterpret_cast<const float4*>(&xg[(size_t)c * TIME + j]);
        xs[j + 0][c] = v.x; xs[j + 1][c] = v.y;
        xs[j + 2][c] = v.z; xs[j + 3][c] = v.w;
    }
    __syncthreads();

    const int t = wid;
    const float invXR = 1.f / XR;

    // ---- moments (j = 1..15; j=0 is the constant 512) ----
    float M[NC];
    #pragma unroll
    for (int j = 1; j < NC; j++) M[j] = 0.f;
    #pragma unroll
    for (int k = 0; k < 16; k++) {
        float xi = fminf(fmaxf(xs[t][lane + 32 * k] * invXR, -1.f), 1.f);
        float tm = 1.f, tc = xi;
        M[1] += xi;
        #pragma unroll
        for (int j = 2; j < NC; j++) {
            float tn = fmaf(2.f * xi, tc, -tm);
            M[j] += tn; tm = tc; tc = tn;
        }
    }
    #pragma unroll
    for (int off = 16; off; off >>= 1) {
        #pragma unroll
        for (int j = 1; j < NC; j++)
            M[j] += __shfl_xor_sync(0xffffffffu, M[j], off);
    }

    // ---- matvecs: lanes 0..15 -> A_j', lanes 16..31 -> B_j' ----
    {
        int jj = lane & 15;
        const float* Gp = (lane < 16) ? sGn : sGd;
        float a = Gp[jj * NC] * (float)CH;     // M_0 = CH
        #pragma unroll
        for (int j = 1; j < NC; j++) a = fmaf(Gp[jj * NC + j], M[j], a);
        float* dst = (lane < 16) ? &sA[t][jj] : &sB[t][jj];
        *dst = a;
    }
    __syncwarp();

    float Ar[NC], Br[NC];
    #pragma unroll
    for (int j = 0; j < NC; j++) { Ar[j] = sA[t][j]; Br[j] = sB[t][j]; }

    // ---- per-element eval ----
    #pragma unroll
    for (int k = 0; k < 16; k++) {
        int c = lane + 32 * k;
        float xi = fminf(fmaxf(xs[t][c] * invXR, -1.f), 1.f);
        float tm = 1.f, tc = xi;
        float num = fmaf(Ar[1], xi, Ar[0]);
        float den = fmaf(Br[1], xi, Br[0]);
        #pragma unroll
        for (int j = 2; j < NC; j++) {
            float tn = fmaf(2.f * xi, tc, -tm);
            num = fmaf(Ar[j], tn, num);
            den = fmaf(Br[j], tn, den);
            tm = tc; tc = tn;
        }
        xs[t][c] = __fdividef(num, den);
    }
    __syncthreads();

    // Coalesced bf16 store: g_attnT[b][t0+tt][c]
    __nv_bfloat162* op = reinterpret_cast<__nv_bfloat162*>(
        g_attnT + ((size_t)b * TIME + t0) * CH);
    for (int i = tid; i < TT * (CH / 2); i += 256) {
        int tt = i >> 8, cp = i & 255;
        op[tt * 256 + cp] =
            __floats2bfloat162_rn(xs[tt][2 * cp], xs[tt][2 * cp + 1]);
    }
}

// ---------------------------------------------------------------------------
// Kernel B (UNCHANGED — measured 22.3us):
// out[b,o,t] = x[b,o,t] + b_proj[o] + sum_c W[o,c]*attn[b,c,t]
// bf16 mma m16n8k16 + ldmatrix.x4 + 3-stage cp.async pipeline.
// ---------------------------------------------------------------------------
#define PBM 64
#define PBN 64
#define PBK 64
#define KST (PBK + 8)
#define NSTG 3
#define BUF_HALVES (PBM * KST)
#define SMEM_BYTES (NSTG * 2 * BUF_HALVES * 2)

__device__ __forceinline__ void cp16(uint32_t dst, const void* src) {
    asm volatile("cp.async.cg.shared.global [%0], [%1], 16;" :: "r"(dst), "l"(src));
}
__device__ __forceinline__ void ldsm_x4(uint32_t r[4], uint32_t addr) {
    asm volatile("ldmatrix.sync.aligned.m8n8.x4.shared.b16 {%0,%1,%2,%3}, [%4];"
                 : "=r"(r[0]), "=r"(r[1]), "=r"(r[2]), "=r"(r[3]) : "r"(addr));
}
__device__ __forceinline__ void mma_bf16(float c[4], const uint32_t a[4], const uint32_t b0, const uint32_t b1) {
    asm("mma.sync.aligned.m16n8k16.row.col.f32.bf16.bf16.f32 "
        "{%0,%1,%2,%3}, {%4,%5,%6,%7}, {%8,%9}, {%0,%1,%2,%3};"
        : "+f"(c[0]), "+f"(c[1]), "+f"(c[2]), "+f"(c[3])
        : "r"(a[0]), "r"(a[1]), "r"(a[2]), "r"(a[3]), "r"(b0), "r"(b1));
}

__global__ __launch_bounds__(128) void proj_kernel(
    const float* __restrict__ bp,
    const float* __restrict__ x, float* __restrict__ out)
{
    extern __shared__ __nv_bfloat16 smem[];
    __nv_bfloat16* Abuf = smem;
    __nv_bfloat16* Bbuf = smem + NSTG * BUF_HALVES;

    const int b   = blockIdx.z;
    const int m0  = blockIdx.y * PBM;
    const int n0  = blockIdx.x * PBN;
    const int tid = threadIdx.x;
    const int wid  = tid >> 5;
    const int lane = tid & 31;
    const int g  = lane >> 2;
    const int tg = lane & 3;
    const int wm = (wid >> 1) * 32;
    const int wn = (wid & 1) * 32;

    const __nv_bfloat16* Bg = g_attnT + (size_t)b * TIME * CH;

    const int srow = tid >> 1;
    const int skb  = (tid & 1) * 32;

    const uint32_t sa0 = (uint32_t)__cvta_generic_to_shared(Abuf);
    const uint32_t sb0 = (uint32_t)__cvta_generic_to_shared(Bbuf);
    const uint32_t stg_bytes = BUF_HALVES * 2;

    float acc[2][4][4];
    #pragma unroll
    for (int i = 0; i < 2; i++)
        #pragma unroll
        for (int j = 0; j < 4; j++)
            #pragma unroll
            for (int r = 0; r < 4; r++) acc[i][j][r] = 0.f;

    auto stage = [&](int s, int k0) {
        const __nv_bfloat16* sA = &g_Wbf[(size_t)(m0 + srow) * CH + k0 + skb];
        const __nv_bfloat16* sB = &Bg[(size_t)(n0 + srow) * CH + k0 + skb];
        uint32_t da = sa0 + s * stg_bytes + (srow * KST + skb) * 2;
        uint32_t db = sb0 + s * stg_bytes + (srow * KST + skb) * 2;
        #pragma unroll
        for (int i = 0; i < 4; i++) {
            cp16(da + i * 16, sA + i * 8);
            cp16(db + i * 16, sB + i * 8);
        }
    };

    stage(0, 0);
    asm volatile("cp.async.commit_group;");
    stage(1, PBK);
    asm volatile("cp.async.commit_group;");

    const int a_row = wm + (lane & 15);
    const int a_k   = ((lane >> 4) & 1) * 8;
    const int b_row = wn + (lane & 7) + ((lane >> 4) & 1) * 8;
    const int b_k   = ((lane >> 3) & 1) * 8;

    const int NIT = CH / PBK;   // 8
    int s = 0;
    for (int it = 0; it < NIT; it++) {
        if (it + 1 < NIT) {
            asm volatile("cp.async.wait_group 1;");
        } else {
            asm volatile("cp.async.wait_group 0;");
        }
        __syncthreads();

        if (it + 2 < NIT) {
            int s2 = s + 2 >= NSTG ? s + 2 - NSTG : s + 2;
            stage(s2, (it + 2) * PBK);
            asm volatile("cp.async.commit_group;");
        }

        const uint32_t ab = sa0 + s * stg_bytes;
        const uint32_t bb = sb0 + s * stg_bytes;

        #pragma unroll
        for (int kk = 0; kk < PBK; kk += 16) {
            uint32_t a[2][4], bf[2][4];
            #pragma unroll
            for (int fm = 0; fm < 2; fm++)
                ldsm_x4(a[fm], ab + ((a_row + fm * 16) * KST + kk + a_k) * 2);
            #pragma unroll
            for (int bh = 0; bh < 2; bh++)
                ldsm_x4(bf[bh], bb + ((b_row + bh * 16) * KST + kk + b_k) * 2);
            #pragma unroll
            for (int fm = 0; fm < 2; fm++)
                #pragma unroll
                for (int bh = 0; bh < 2; bh++) {
                    mma_bf16(acc[fm][bh * 2 + 0], a[fm], bf[bh][0], bf[bh][1]);
                    mma_bf16(acc[fm][bh * 2 + 1], a[fm], bf[bh][2], bf[bh][3]);
                }
        }
        s = (s + 1 >= NSTG) ? 0 : s + 1;
    }

    const float* xb = x + (size_t)b * CH * TIME;
    float*       ob = out + (size_t)b * CH * TIME;
    #pragma unroll
    for (int fm = 0; fm < 2; fm++) {
        int row0 = m0 + wm + fm * 16 + g;
        float bias0 = bp[row0];
        float bias1 = bp[row0 + 8];
        #pragma unroll
        for (int fn = 0; fn < 4; fn++) {
            int col = n0 + wn + fn * 8 + tg * 2;
            size_t off0 = (size_t)row0 * TIME + col;
            size_t off1 = (size_t)(row0 + 8) * TIME + col;
            float2 x0 = *reinterpret_cast<const float2*>(&xb[off0]);
            float2 x1 = *reinterpret_cast<const float2*>(&xb[off1]);
            float2 o0, o1;
            o0.x = x0.x + bias0 + acc[fm][fn][0];
            o0.y = x0.y + bias0 + acc[fm][fn][1];
            o1.x = x1.x + bias1 + acc[fm][fn][2];
            o1.y = x1.y + bias1 + acc[fm][fn][3];
            *reinterpret_cast<float2*>(&ob[off0]) = o0;
            *reinterpret_cast<float2*>(&ob[off1]) = o1;
        }
    }
}

// ---------------------------------------------------------------------------
extern "C" void kernel_launch(void* const* d_in, const int* in_sizes, int n_in,
                              void* d_out, int out_size) {
    const float* x  = (const float*)d_in[0];
    const float* wq = (const float*)d_in[1];
    const float* bq = (const float*)d_in[2];
    const float* wk = (const float*)d_in[3];
    const float* bk = (const float*)d_in[4];
    const float* wv = (const float*)d_in[5];
    const float* bv = (const float*)d_in[6];
    const float* wp = (const float*)d_in[7];
    const float* bp = (const float*)d_in[8];
    float* out = (float*)d_out;

    cudaFuncSetAttribute(proj_kernel,
                         cudaFuncAttributeMaxDynamicSharedMemorySize,
                         SMEM_BYTES);

    cheb_prologue<<<1, 256>>>(wq, bq, wk, bk, wv, bv);

    attn_kernel<<<BATCH * (TIME / TT), 256>>>(x, wp);

    dim3 grid(TIME / PBN, CH / PBM, BATCH);
    proj_kernel<<<grid, 128, SMEM_BYTES>>>(bp, x, out);
}